// round 15
// baseline (speedup 1.0000x reference)
#include <cuda_runtime.h>

#define IMG_W 512
#define IMG_H 512
#define N_IMG 48            // 16 batch * 3 channels
#define HT 8                // output rows per block strip
#define N_STRIPS (IMG_H / HT)
#define NBLK (N_STRIPS * N_IMG)
#define SW 528              // smem columns: s = x+8; float4-aligned rows
#define NT 256              // 8 warps
#define SM_FLOATS (4 * HT * SW)
#define SMEM_BYTES ((SM_FLOATS + 8) * 4)

// zero-initialized at module load; last block of each launch resets them,
// so every graph replay starts from zero (deterministic).
__device__ double g_acc;
__device__ unsigned int g_cnt;

// literal taps -> FFMA immediate-multiplier form (rt_SMSP = 1, 2x the 3-reg rate)
#define WG_INIT {0.00102838f, 0.00759876f, 0.03600077f, 0.10936069f, \
                 0.21300554f, 0.26601173f, 0.21300554f, 0.10936069f, \
                 0.03600077f, 0.00759876f, 0.00102838f}

// 11-tap conv, 8 outputs, k-outer / r-inner: 8 independent FMA chains (full ILP),
// weight is a compile-time literal in every unrolled statement.
__device__ __forceinline__ void vconv8(const float* __restrict__ v,
                                       float* __restrict__ dst, int stride) {
    const float wg[11] = WG_INIT;
    float a[HT];
    #pragma unroll
    for (int r = 0; r < HT; r++) a[r] = 0.f;
    #pragma unroll
    for (int k = 0; k < 11; k++) {
        #pragma unroll
        for (int r = 0; r < HT; r++) a[r] = fmaf(wg[k], v[r + k], a[r]);
    }
    #pragma unroll
    for (int r = 0; r < HT; r++) dst[r * stride] = a[r];
}

// Load 24 floats (6 aligned float4) starting at s = 8*o from one smem row.
__device__ __forceinline__ void load24(const float* __restrict__ row, int o,
                                       float* __restrict__ v) {
    const float4* rp = (const float4*)row + 2 * o;
    #pragma unroll
    for (int b = 0; b < 6; b++) {
        float4 f = rp[b];
        v[4 * b + 0] = f.x; v[4 * b + 1] = f.y;
        v[4 * b + 2] = f.z; v[4 * b + 3] = f.w;
    }
}

// 11-tap conv on v[24] -> 8 outputs (taps for output j are v[3+j .. 13+j]).
__device__ __forceinline__ void hconv8(const float* __restrict__ v,
                                       float* __restrict__ h) {
    const float wg[11] = WG_INIT;
    #pragma unroll
    for (int j = 0; j < 8; j++) h[j] = 0.f;
    #pragma unroll
    for (int k = 0; k < 11; k++) {
        #pragma unroll
        for (int j = 0; j < 8; j++) h[j] = fmaf(wg[k], v[3 + j + k], h[j]);
    }
}

__global__ void __launch_bounds__(NT, 3) ssim_fused(const float* __restrict__ pred,
                                                    const float* __restrict__ tgt,
                                                    float* __restrict__ out) {
    extern __shared__ float sm[];
    float* wsum = sm + SM_FLOATS;

    const int img  = blockIdx.y;
    const int row0 = blockIdx.x * HT;
    const float* P = pred + (size_t)img * (IMG_W * IMG_H);
    const float* T = tgt  + (size_t)img * (IMG_W * IMG_H);
    const bool interior = (row0 >= 5) && (row0 + HT + 5 <= IMG_H);

    // -------- Vertical pass (scalar, one column per thread): global -> smem --------
    for (int s = threadIdx.x; s < SW; s += NT) {
        const int x = s - 8;
        if (x < 0 || x >= IMG_W) {
            #pragma unroll
            for (int r = 0; r < HT; r++) {
                sm[(0 * HT + r) * SW + s] = 0.f;
                sm[(1 * HT + r) * SW + s] = 0.f;
                sm[(2 * HT + r) * SW + s] = 0.f;
                sm[(3 * HT + r) * SW + s] = 0.f;
            }
            continue;
        }
        float pv[HT + 10], tv[HT + 10];
        if (interior) {
            const float* pc = P + (row0 - 5) * IMG_W + x;
            const float* tc = T + (row0 - 5) * IMG_W + x;
            #pragma unroll
            for (int i = 0; i < HT + 10; i++) {
                pv[i] = pc[i * IMG_W];
                tv[i] = tc[i * IMG_W];
            }
        } else {
            #pragma unroll
            for (int i = 0; i < HT + 10; i++) {
                const int row = row0 - 5 + i;
                const bool ok = (row >= 0) && (row < IMG_H);
                pv[i] = ok ? P[row * IMG_W + x] : 0.f;
                tv[i] = ok ? T[row * IMG_W + x] : 0.f;
            }
        }
        vconv8(pv, sm + (0 * HT) * SW + s, SW);   // mu_p
        vconv8(tv, sm + (1 * HT) * SW + s, SW);   // mu_t
        // in-place transform: pv <- p^2 + t^2, tv <- p*t (each input used once)
        #pragma unroll
        for (int i = 0; i < HT + 10; i++) {
            const float p = pv[i], t = tv[i];
            pv[i] = fmaf(p, p, t * t);
            tv[i] = p * t;
        }
        vconv8(pv, sm + (2 * HT) * SW + s, SW);   // blur(p^2 + t^2)
        vconv8(tv, sm + (3 * HT) * SW + s, SW);   // blur(p*t)
    }
    __syncthreads();

    // ---- Horizontal pass: 8-wide, channels sequential through one v[24] ----
    const float C1 = 1e-4f, C2 = 9e-4f;
    float acc = 0.f;
    #pragma unroll 1
    for (int task = threadIdx.x; task < HT * (IMG_W / 8); task += NT) {  // 512
        const int r = task >> 6;      // row within strip
        const int o = task & 63;      // oct: outputs x = 8o .. 8o+7
        float v[24], ms[8], mq[8], hx[8], hy[8];
        load24(sm + (2 * HT + r) * SW, o, v);  hconv8(v, ms);  // blur(p^2+t^2)
        load24(sm + (3 * HT + r) * SW, o, v);  hconv8(v, mq);  // blur(p*t)
        load24(sm + (0 * HT + r) * SW, o, v);  hconv8(v, hx);  // mu_x
        load24(sm + (1 * HT + r) * SW, o, v);  hconv8(v, hy);  // mu_y
        #pragma unroll
        for (int j = 0; j < 8; j++) {
            float mx  = hx[j], my = hy[j];
            float mx2 = mx * mx, my2 = my * my, mxy = mx * my;
            float sgs  = ms[j] - mx2 - my2;   // sg_x + sg_y
            float sgxy = mq[j] - mxy;
            float num = (2.f * mxy + C1) * (2.f * sgxy + C2);
            float den = (mx2 + my2 + C1) * (sgs + C2);
            acc += __fdividef(num, den);
        }
    }

    // -------- block reduction + last-block finalize --------
    #pragma unroll
    for (int off = 16; off; off >>= 1)
        acc += __shfl_down_sync(0xffffffffu, acc, off);
    if ((threadIdx.x & 31) == 0) wsum[threadIdx.x >> 5] = acc;
    __syncthreads();

    if (threadIdx.x == 0) {
        float s = 0.f;
        #pragma unroll
        for (int i = 0; i < NT / 32; i++) s += wsum[i];
        atomicAdd(&g_acc, (double)s);
        __threadfence();
        unsigned int t = atomicAdd(&g_cnt, 1u);
        if (t == NBLK - 1) {
            double tot = atomicAdd(&g_acc, 0.0);   // coherent read (returns old)
            out[0] = 1.0f - (float)(tot / ((double)N_IMG * IMG_W * IMG_H));
            g_acc = 0.0;    // reset for next graph replay
            g_cnt = 0u;
        }
    }
}

extern "C" void kernel_launch(void* const* d_in, const int* in_sizes, int n_in,
                              void* d_out, int out_size) {
    const float* pred = (const float*)d_in[0];
    const float* tgt  = (const float*)d_in[1];

    // 66 KB dynamic smem > 48 KB default: opt-in (host attribute, capture-safe)
    cudaFuncSetAttribute(ssim_fused, cudaFuncAttributeMaxDynamicSharedMemorySize,
                         SMEM_BYTES);

    dim3 grid(N_STRIPS, N_IMG);
    ssim_fused<<<grid, NT, SMEM_BYTES>>>(pred, tgt, (float*)d_out);
}

// round 16
// speedup vs baseline: 1.0966x; 1.0966x over previous
#include <cuda_runtime.h>

#define IMG_W 512
#define IMG_H 512
#define N_IMG 48            // 16 batch * 3 channels
#define HT 4                // output rows per block strip (halved: smem/occupancy)
#define N_STRIPS (IMG_H / HT)
#define NBLK (N_STRIPS * N_IMG)
#define SW 528              // smem columns: s = x+8; float4-aligned rows
#define NT 256              // 8 warps
#define SM_FLOATS (4 * HT * SW)
#define SMEM_BYTES ((SM_FLOATS + 8) * 4)

// zero-initialized at module load; last block of each launch resets them,
// so every graph replay starts from zero (deterministic).
__device__ double g_acc;
__device__ unsigned int g_cnt;

// literal taps -> FFMA immediate-multiplier form (rt_SMSP = 1, 2x the 3-reg rate)
#define WG_INIT {0.00102838f, 0.00759876f, 0.03600077f, 0.10936069f, \
                 0.21300554f, 0.26601173f, 0.21300554f, 0.10936069f, \
                 0.03600077f, 0.00759876f, 0.00102838f}

// 11-tap conv, HT outputs, k-outer / r-inner: HT independent FMA chains,
// weight is a compile-time literal in every unrolled statement.
__device__ __forceinline__ void vconvHT(const float* __restrict__ v,
                                        float* __restrict__ dst, int stride) {
    const float wg[11] = WG_INIT;
    float a[HT];
    #pragma unroll
    for (int r = 0; r < HT; r++) a[r] = 0.f;
    #pragma unroll
    for (int k = 0; k < 11; k++) {
        #pragma unroll
        for (int r = 0; r < HT; r++) a[r] = fmaf(wg[k], v[r + k], a[r]);
    }
    #pragma unroll
    for (int r = 0; r < HT; r++) dst[r * stride] = a[r];
}

__global__ void __launch_bounds__(NT, 4) ssim_fused(const float* __restrict__ pred,
                                                    const float* __restrict__ tgt,
                                                    float* __restrict__ out) {
    extern __shared__ float sm[];
    float* wsum = sm + SM_FLOATS;
    const float wg[11] = WG_INIT;

    const int img  = blockIdx.y;
    const int row0 = blockIdx.x * HT;
    const float* P = pred + (size_t)img * (IMG_W * IMG_H);
    const float* T = tgt  + (size_t)img * (IMG_W * IMG_H);
    const bool interior = (row0 >= 5) && (row0 + HT + 5 <= IMG_H);

    // -------- Vertical pass (scalar, one column per thread): global -> smem --------
    for (int s = threadIdx.x; s < SW; s += NT) {
        const int x = s - 8;
        if (x < 0 || x >= IMG_W) {
            #pragma unroll
            for (int r = 0; r < HT; r++) {
                sm[(0 * HT + r) * SW + s] = 0.f;
                sm[(1 * HT + r) * SW + s] = 0.f;
                sm[(2 * HT + r) * SW + s] = 0.f;
                sm[(3 * HT + r) * SW + s] = 0.f;
            }
            continue;
        }
        float pv[HT + 10], tv[HT + 10];
        if (interior) {
            const float* pc = P + (row0 - 5) * IMG_W + x;
            const float* tc = T + (row0 - 5) * IMG_W + x;
            #pragma unroll
            for (int i = 0; i < HT + 10; i++) {
                pv[i] = pc[i * IMG_W];
                tv[i] = tc[i * IMG_W];
            }
        } else {
            #pragma unroll
            for (int i = 0; i < HT + 10; i++) {
                const int row = row0 - 5 + i;
                const bool ok = (row >= 0) && (row < IMG_H);
                pv[i] = ok ? P[row * IMG_W + x] : 0.f;
                tv[i] = ok ? T[row * IMG_W + x] : 0.f;
            }
        }
        vconvHT(pv, sm + (0 * HT) * SW + s, SW);   // mu_p
        vconvHT(tv, sm + (1 * HT) * SW + s, SW);   // mu_t
        // in-place transform: pv <- p^2 + t^2, tv <- p*t (each input used once)
        #pragma unroll
        for (int i = 0; i < HT + 10; i++) {
            const float p = pv[i], t = tv[i];
            pv[i] = fmaf(p, p, t * t);
            tv[i] = p * t;
        }
        vconvHT(pv, sm + (2 * HT) * SW + s, SW);   // blur(p^2 + t^2)
        vconvHT(tv, sm + (3 * HT) * SW + s, SW);   // blur(p*t)
    }
    __syncthreads();

    // ---- Horizontal pass: 4-wide quads (lane-contiguous => conflict-free) ----
    const float C1 = 1e-4f, C2 = 9e-4f;
    float acc = 0.f;
    #pragma unroll 1
    for (int task = threadIdx.x; task < HT * (IMG_W / 4); task += NT) {  // 512
        const int r = task >> 7;       // row within strip
        const int q = task & 127;      // quad: outputs x0 = 4q .. 4q+3
        float h[4][4];
        #pragma unroll
        for (int ch = 0; ch < 4; ch++) {
            const float4* rowp = (const float4*)(sm + (ch * HT + r) * SW);
            float v[20];
            #pragma unroll
            for (int b = 0; b < 5; b++) {
                float4 f = rowp[q + b];   // s = 4q..4q+19 covers taps [4q+3, 4q+16]
                v[4 * b + 0] = f.x; v[4 * b + 1] = f.y;
                v[4 * b + 2] = f.z; v[4 * b + 3] = f.w;
            }
            #pragma unroll
            for (int j = 0; j < 4; j++) {
                float a = 0.f;
                #pragma unroll
                for (int k = 0; k < 11; k++) a = fmaf(wg[k], v[3 + j + k], a);
                h[ch][j] = a;
            }
        }
        #pragma unroll
        for (int j = 0; j < 4; j++) {
            float mx  = h[0][j], my = h[1][j];
            float mx2 = mx * mx, my2 = my * my, mxy = mx * my;
            float sgs  = h[2][j] - mx2 - my2;   // sg_x + sg_y
            float sgxy = h[3][j] - mxy;
            float num = (2.f * mxy + C1) * (2.f * sgxy + C2);
            float den = (mx2 + my2 + C1) * (sgs + C2);
            acc += __fdividef(num, den);
        }
    }

    // -------- block reduction + last-block finalize --------
    #pragma unroll
    for (int off = 16; off; off >>= 1)
        acc += __shfl_down_sync(0xffffffffu, acc, off);
    if ((threadIdx.x & 31) == 0) wsum[threadIdx.x >> 5] = acc;
    __syncthreads();

    if (threadIdx.x == 0) {
        float s = 0.f;
        #pragma unroll
        for (int i = 0; i < NT / 32; i++) s += wsum[i];
        atomicAdd(&g_acc, (double)s);
        __threadfence();
        unsigned int t = atomicAdd(&g_cnt, 1u);
        if (t == NBLK - 1) {
            double tot = atomicAdd(&g_acc, 0.0);   // coherent read (returns old)
            out[0] = 1.0f - (float)(tot / ((double)N_IMG * IMG_W * IMG_H));
            g_acc = 0.0;    // reset for next graph replay
            g_cnt = 0u;
        }
    }
}

extern "C" void kernel_launch(void* const* d_in, const int* in_sizes, int n_in,
                              void* d_out, int out_size) {
    const float* pred = (const float*)d_in[0];
    const float* tgt  = (const float*)d_in[1];

    cudaFuncSetAttribute(ssim_fused, cudaFuncAttributeMaxDynamicSharedMemorySize,
                         SMEM_BYTES);

    dim3 grid(N_STRIPS, N_IMG);
    ssim_fused<<<grid, NT, SMEM_BYTES>>>(pred, tgt, (float*)d_out);
}